// round 2
// baseline (speedup 1.0000x reference)
#include <cuda_runtime.h>
#include <math.h>

#define N_NODES 100000
#define D 128
#define E_EDGES 1600000
#define EPS 1e-5f

// ---------------- scratch (device globals: no allocs allowed) ----------------
__device__ float  g_agg[(size_t)N_NODES * D];   // 51.2 MB: x + neighbor sum
__device__ float  g_h2 [(size_t)N_NODES * D];   // 51.2 MB: pre-BN activations
__device__ double g_colsum[D];
__device__ double g_colsq [D];
__device__ float  g_scale[D];
__device__ float  g_shift[D];
__device__ int    g_idx_is64;                   // 1 if edge_index stored as int64

// ---------------- kernel 0: detect edge-index dtype -------------------------
// int64 (2,E) row-major: words [2i+1] are high halves of non-negative indices
// < N  -> all zero. int32: words [2i+1] are random indices in [0,N).
__global__ void detect_kernel(const int* __restrict__ ei32) {
    if (threadIdx.x == 0) {
        int is64 = 1;
        #pragma unroll 1
        for (int i = 0; i < 128; i++) {
            if (ei32[2 * i + 1] != 0) { is64 = 0; break; }
        }
        g_idx_is64 = is64;
    }
}

// ---------------- kernel 1: agg = x (residual), zero BN accumulators --------
__global__ void init_kernel(const float* __restrict__ x) {
    size_t i = (size_t)blockIdx.x * blockDim.x + threadIdx.x;
    size_t n4 = (size_t)N_NODES * D / 4;
    if (i < n4) {
        reinterpret_cast<float4*>(g_agg)[i] =
            reinterpret_cast<const float4*>(x)[i];
    }
    if (blockIdx.x == 0 && threadIdx.x < D) {
        g_colsum[threadIdx.x] = 0.0;
        g_colsq [threadIdx.x] = 0.0;
    }
}

// ---------------- kernel 2: scatter-add, one warp per edge ------------------
__device__ __forceinline__ void red_add_v4(float* addr, float4 v) {
    asm volatile("red.global.add.v4.f32 [%0], {%1,%2,%3,%4};"
                 :: "l"(addr), "f"(v.x), "f"(v.y), "f"(v.z), "f"(v.w)
                 : "memory");
}

__global__ void scatter_kernel(const float* __restrict__ x,
                               const void* __restrict__ ei_raw) {
    int w    = (blockIdx.x * blockDim.x + threadIdx.x) >> 5;
    int lane = threadIdx.x & 31;
    if (w >= E_EDGES) return;
    int r, c;
    if (g_idx_is64) {
        const long long* ei = (const long long*)ei_raw;
        r = (int)__ldg(ei + w);
        c = (int)__ldg(ei + E_EDGES + w);
    } else {
        const int* ei = (const int*)ei_raw;
        r = __ldg(ei + w);
        c = __ldg(ei + E_EDGES + w);
    }
    float4 v = *reinterpret_cast<const float4*>(x + (size_t)c * D + lane * 4);
    red_add_v4(g_agg + (size_t)r * D + lane * 4, v);
}

// ---------------- kernel 3: fused MLP (2 GEMMs + ReLU) + BN partial sums ----
// Persistent blocks, 512 threads, 64-row tiles, 4x4 register blocking.
#define TILE_ROWS 64
#define MLP_THREADS 512
#define SMEM_FLOATS (16384 + 16384 + 8192 + 8192 + 128 + 128 + 128 + 128)

__global__ __launch_bounds__(MLP_THREADS, 1)
void mlp_kernel(const float* __restrict__ W1, const float* __restrict__ b1,
                const float* __restrict__ W2, const float* __restrict__ b2) {
    extern __shared__ float sm[];
    float* W1s  = sm;                 // [128][128]
    float* W2s  = W1s + 16384;        // [128][128]
    float* As   = W2s + 16384;        // [64][128]
    float* Bs   = As  + 8192;         // [64][128]
    float* b1s  = Bs  + 8192;         // [128]
    float* b2s  = b1s + 128;          // [128]
    float* csum = b2s + 128;          // [128]
    float* csq  = csum + 128;         // [128]

    const int tid = threadIdx.x;
    const int tx  = tid & 31;   // column group: cols 4*tx .. 4*tx+3
    const int ty  = tid >> 5;   // row group:    rows 4*ty .. 4*ty+3 (0..15)

    for (int i = tid; i < 16384 / 4; i += MLP_THREADS) {
        reinterpret_cast<float4*>(W1s)[i] = reinterpret_cast<const float4*>(W1)[i];
        reinterpret_cast<float4*>(W2s)[i] = reinterpret_cast<const float4*>(W2)[i];
    }
    if (tid < 128) {
        b1s[tid]  = b1[tid];
        b2s[tid]  = b2[tid];
        csum[tid] = 0.0f;
        csq [tid] = 0.0f;
    }
    __syncthreads();

    const int ntiles = (N_NODES + TILE_ROWS - 1) / TILE_ROWS;

    for (int t = blockIdx.x; t < ntiles; t += gridDim.x) {
        const int base = t * TILE_ROWS;
        __syncthreads();   // previous iteration fully done with As/Bs

        for (int i = tid; i < TILE_ROWS * D / 4; i += MLP_THREADS) {
            int r   = i >> 5;
            int q   = i & 31;
            int row = base + r;
            float4 v = make_float4(0.f, 0.f, 0.f, 0.f);
            if (row < N_NODES)
                v = reinterpret_cast<const float4*>(g_agg)[(size_t)row * 32 + q];
            reinterpret_cast<float4*>(As)[i] = v;
        }
        __syncthreads();

        // ---- stage 1: B = relu(A @ W1 + b1) ----
        float acc[4][4];
        {
            float bb0 = b1s[4 * tx + 0], bb1 = b1s[4 * tx + 1];
            float bb2 = b1s[4 * tx + 2], bb3 = b1s[4 * tx + 3];
            #pragma unroll
            for (int i = 0; i < 4; i++) {
                acc[i][0] = bb0; acc[i][1] = bb1; acc[i][2] = bb2; acc[i][3] = bb3;
            }
        }
        #pragma unroll 4
        for (int k = 0; k < D; k++) {
            float4 w = reinterpret_cast<const float4*>(W1s + k * D)[tx];
            #pragma unroll
            for (int i = 0; i < 4; i++) {
                float a = As[(ty * 4 + i) * D + k];
                acc[i][0] += a * w.x;
                acc[i][1] += a * w.y;
                acc[i][2] += a * w.z;
                acc[i][3] += a * w.w;
            }
        }
        #pragma unroll
        for (int i = 0; i < 4; i++) {
            float4 v;
            v.x = fmaxf(acc[i][0], 0.f);
            v.y = fmaxf(acc[i][1], 0.f);
            v.z = fmaxf(acc[i][2], 0.f);
            v.w = fmaxf(acc[i][3], 0.f);
            reinterpret_cast<float4*>(Bs + (ty * 4 + i) * D)[tx] = v;
        }
        __syncthreads();

        // ---- stage 2: C = B @ W2 + b2 ----
        {
            float bb0 = b2s[4 * tx + 0], bb1 = b2s[4 * tx + 1];
            float bb2 = b2s[4 * tx + 2], bb3 = b2s[4 * tx + 3];
            #pragma unroll
            for (int i = 0; i < 4; i++) {
                acc[i][0] = bb0; acc[i][1] = bb1; acc[i][2] = bb2; acc[i][3] = bb3;
            }
        }
        #pragma unroll 4
        for (int k = 0; k < D; k++) {
            float4 w = reinterpret_cast<const float4*>(W2s + k * D)[tx];
            #pragma unroll
            for (int i = 0; i < 4; i++) {
                float a = Bs[(ty * 4 + i) * D + k];
                acc[i][0] += a * w.x;
                acc[i][1] += a * w.y;
                acc[i][2] += a * w.z;
                acc[i][3] += a * w.w;
            }
        }

        // ---- epilogue: write h2, accumulate BN partial sums ----
        float s0 = 0.f, s1 = 0.f, s2 = 0.f, s3 = 0.f;
        float q0 = 0.f, q1 = 0.f, q2 = 0.f, q3 = 0.f;
        #pragma unroll
        for (int i = 0; i < 4; i++) {
            int row = base + ty * 4 + i;
            if (row < N_NODES) {
                float4 v = make_float4(acc[i][0], acc[i][1], acc[i][2], acc[i][3]);
                reinterpret_cast<float4*>(g_h2 + (size_t)row * D)[tx] = v;
                s0 += v.x; s1 += v.y; s2 += v.z; s3 += v.w;
                q0 += v.x * v.x; q1 += v.y * v.y; q2 += v.z * v.z; q3 += v.w * v.w;
            }
        }
        atomicAdd(&csum[4 * tx + 0], s0); atomicAdd(&csq[4 * tx + 0], q0);
        atomicAdd(&csum[4 * tx + 1], s1); atomicAdd(&csq[4 * tx + 1], q1);
        atomicAdd(&csum[4 * tx + 2], s2); atomicAdd(&csq[4 * tx + 2], q2);
        atomicAdd(&csum[4 * tx + 3], s3); atomicAdd(&csq[4 * tx + 3], q3);
    }

    __syncthreads();
    if (tid < 128) {
        atomicAdd(&g_colsum[tid], (double)csum[tid]);
        atomicAdd(&g_colsq [tid], (double)csq [tid]);
    }
}

// ---------------- kernel 4: BN coefficients ---------------------------------
__global__ void bn_prep_kernel(const float* __restrict__ gamma,
                               const float* __restrict__ beta) {
    int j = threadIdx.x;
    if (j < D) {
        double mean = g_colsum[j] / (double)N_NODES;
        double var  = g_colsq[j] / (double)N_NODES - mean * mean;
        float inv   = rsqrtf((float)var + EPS);
        float sc    = gamma[j] * inv;
        g_scale[j]  = sc;
        g_shift[j]  = beta[j] - (float)mean * sc;
    }
}

// ---------------- kernel 5: apply BN ----------------------------------------
__global__ void bn_apply_kernel(float* __restrict__ out) {
    __shared__ float sc[D], sh[D];
    if (threadIdx.x < D) {
        sc[threadIdx.x] = g_scale[threadIdx.x];
        sh[threadIdx.x] = g_shift[threadIdx.x];
    }
    __syncthreads();
    size_t i  = (size_t)blockIdx.x * blockDim.x + threadIdx.x;
    size_t n4 = (size_t)N_NODES * D / 4;
    if (i < n4) {
        int c = (int)((i & 31) << 2);
        float4 h = reinterpret_cast<const float4*>(g_h2)[i];
        float4 o;
        o.x = h.x * sc[c + 0] + sh[c + 0];
        o.y = h.y * sc[c + 1] + sh[c + 1];
        o.z = h.z * sc[c + 2] + sh[c + 2];
        o.w = h.w * sc[c + 3] + sh[c + 3];
        reinterpret_cast<float4*>(out)[i] = o;
    }
}

// ---------------- launcher ---------------------------------------------------
extern "C" void kernel_launch(void* const* d_in, const int* in_sizes, int n_in,
                              void* d_out, int out_size) {
    const float* x     = (const float*)d_in[0];
    const void*  ei    = d_in[1];
    const float* W1    = (const float*)d_in[2];
    const float* b1    = (const float*)d_in[3];
    const float* W2    = (const float*)d_in[4];
    const float* b2    = (const float*)d_in[5];
    const float* gamma = (const float*)d_in[6];
    const float* beta  = (const float*)d_in[7];
    float* out = (float*)d_out;

    cudaFuncSetAttribute(mlp_kernel,
                         cudaFuncAttributeMaxDynamicSharedMemorySize,
                         SMEM_FLOATS * (int)sizeof(float));

    // 0) detect edge-index dtype (int32 vs int64)
    detect_kernel<<<1, 32>>>((const int*)ei);

    // 1) agg = x, zero BN accumulators
    {
        int n4 = N_NODES * D / 4;
        init_kernel<<<(n4 + 255) / 256, 256>>>(x);
    }
    // 2) scatter-add: one warp per edge
    {
        int warps_per_block = 8;                  // 256 threads
        int blocks = (E_EDGES + warps_per_block - 1) / warps_per_block;
        scatter_kernel<<<blocks, 256>>>(x, ei);
    }
    // 3) fused MLP + BN partial sums (persistent, 1 CTA/SM)
    mlp_kernel<<<152, MLP_THREADS, SMEM_FLOATS * (int)sizeof(float)>>>(W1, b1, W2, b2);
    // 4) BN coefficients
    bn_prep_kernel<<<1, 128>>>(gamma, beta);
    // 5) apply BN
    {
        int n4 = N_NODES * D / 4;
        bn_apply_kernel<<<(n4 + 255) / 256, 256>>>(out);
    }
}

// round 4
// speedup vs baseline: 1.1215x; 1.1215x over previous
#include <cuda_runtime.h>
#include <cuda_bf16.h>
#include <cstdint>
#include <math.h>

#define N_NODES 100000
#define D 128
#define E_EDGES 1600000
#define EPS 1e-5f
#define NTILES ((N_NODES + 127) / 128)   // 782

// ---------------- scratch (device globals: no allocs allowed) ----------------
__device__ float  g_agg[(size_t)N_NODES * D];   // x + agg; then mid; then h2 (in-place)
__device__ double g_colsum[D];
__device__ double g_colsq [D];
__device__ float  g_scale[D];
__device__ float  g_shift[D];
__device__ int    g_idx_is64;

// ============================ helpers ========================================
__device__ __forceinline__ float to_tf32(float v) {
    float r;
    asm("cvt.rna.tf32.f32 %0, %1;" : "=f"(r) : "f"(v));
    return r;
}
// XOR-swizzled element index within a 128x128 tile (stride 128 floats).
// Conflict-free for row-major f4 access AND mma-fragment column access.
__device__ __forceinline__ int idxA(int row, int col) {
    return row * 128 + (((col >> 2) ^ (row & 31)) << 2) + (col & 3);
}

__device__ __forceinline__ void mma_tf32(float c[4],
                                         uint32_t a0, uint32_t a1,
                                         uint32_t a2, uint32_t a3,
                                         uint32_t b0, uint32_t b1) {
    asm volatile(
        "mma.sync.aligned.m16n8k8.row.col.f32.tf32.tf32.f32 "
        "{%0,%1,%2,%3}, {%4,%5,%6,%7}, {%8,%9}, {%0,%1,%2,%3};"
        : "+f"(c[0]), "+f"(c[1]), "+f"(c[2]), "+f"(c[3])
        : "r"(a0), "r"(a1), "r"(a2), "r"(a3), "r"(b0), "r"(b1));
}

// ---------------- kernel 0: detect edge-index dtype -------------------------
__global__ void detect_kernel(const int* __restrict__ ei32) {
    if (threadIdx.x == 0) {
        int is64 = 1;
        #pragma unroll 1
        for (int i = 0; i < 128; i++)
            if (ei32[2 * i + 1] != 0) { is64 = 0; break; }
        g_idx_is64 = is64;
    }
}

// ---------------- kernel 1: agg = x, zero BN accumulators -------------------
__global__ void init_kernel(const float* __restrict__ x) {
    size_t i = (size_t)blockIdx.x * blockDim.x + threadIdx.x;
    size_t n4 = (size_t)N_NODES * D / 4;
    if (i < n4)
        reinterpret_cast<float4*>(g_agg)[i] = reinterpret_cast<const float4*>(x)[i];
    if (blockIdx.x == 0 && threadIdx.x < D) {
        g_colsum[threadIdx.x] = 0.0;
        g_colsq [threadIdx.x] = 0.0;
    }
}

// ---------------- kernel 2: scatter-add, one warp per edge ------------------
__device__ __forceinline__ void red_add_v4(float* addr, float4 v) {
    asm volatile("red.global.add.v4.f32 [%0], {%1,%2,%3,%4};"
                 :: "l"(addr), "f"(v.x), "f"(v.y), "f"(v.z), "f"(v.w) : "memory");
}
__global__ void scatter_kernel(const float* __restrict__ x,
                               const void* __restrict__ ei_raw) {
    int w    = (blockIdx.x * blockDim.x + threadIdx.x) >> 5;
    int lane = threadIdx.x & 31;
    if (w >= E_EDGES) return;
    int r, c;
    if (g_idx_is64) {
        const long long* ei = (const long long*)ei_raw;
        r = (int)__ldg(ei + w);
        c = (int)__ldg(ei + E_EDGES + w);
    } else {
        const int* ei = (const int*)ei_raw;
        r = __ldg(ei + w);
        c = __ldg(ei + E_EDGES + w);
    }
    float4 v = *reinterpret_cast<const float4*>(x + (size_t)c * D + lane * 4);
    red_add_v4(g_agg + (size_t)r * D + lane * 4, v);
}

// ---------------- stage kernel: in-place 128x128 GEMM via mma.sync tf32 -----
// io <- act(io @ W + b). 3-term tf32 split: Ahi*Whi + Ahi*Wlo + Alo*Whi,
// lo-corrections stored bf16. Optional fused BN column sums (stage 2).
#define STAGE_THREADS 256
// smem floats: WHI 16384 + AHI 16384, then bf16: WLO 16384 + ALO 16384,
// then BS/CS/CQ 128 floats each.
#define SM_FLOATS (16384 + 16384 + (16384 + 16384) / 2 + 128 + 128 + 128)
#define SM_BYTES  (SM_FLOATS * 4)

__global__ __launch_bounds__(STAGE_THREADS, 1)
void stage_mma_kernel(const float* __restrict__ W, const float* __restrict__ bias,
                      int do_relu, int do_bn) {
    extern __shared__ float smf[];
    float* WHI = smf;                                   // [128][128] swizzled
    float* AHI = smf + 16384;                           // [128][128] swizzled (also out tile)
    __nv_bfloat16* WLO = (__nv_bfloat16*)(smf + 32768); // [128][128] swizzled
    __nv_bfloat16* ALO = WLO + 16384;
    float* BS = (float*)(ALO + 16384);                  // 128
    float* CS = BS + 128;                               // 128
    float* CQ = CS + 128;                               // 128

    const int tid    = threadIdx.x;
    const int lane   = tid & 31;
    const int warp   = tid >> 5;       // 0..7
    const int warp_m = warp & 3;       // 4 blocks of 32 rows
    const int warp_n = warp >> 2;      // 2 blocks of 64 cols
    const int gid    = lane >> 2;      // 0..7
    const int tig    = lane & 3;       // 0..3

    float* io = g_agg;

    // ---- load weights once: W[k][n] -> transposed swizzled hi(f32)/lo(bf16)
    for (int i4 = tid; i4 < 4096; i4 += STAGE_THREADS) {
        int k  = i4 >> 5;
        int c4 = i4 & 31;
        float4 v = ((const float4*)W)[i4];
        #pragma unroll
        for (int e = 0; e < 4; e++) {
            float val = (e == 0) ? v.x : (e == 1) ? v.y : (e == 2) ? v.z : v.w;
            int n = c4 * 4 + e;
            float hi = to_tf32(val);
            int o = idxA(n, k);
            WHI[o] = hi;
            WLO[o] = __float2bfloat16(val - hi);
        }
    }
    if (tid < 128) {
        BS[tid] = bias[tid];
        CS[tid] = 0.f;
        CQ[tid] = 0.f;
    }
    __syncthreads();

    for (int t = blockIdx.x; t < NTILES; t += gridDim.x) {
        const int base  = t << 7;
        const int valid = min(128, N_NODES - base);
        __syncthreads();   // protect AHI/ALO from previous tile's readers

        // ---- 1) load tile, split into Ahi (tf32) / Alo (bf16) --------------
        #pragma unroll
        for (int q = 0; q < 16; q++) {
            int f   = q * STAGE_THREADS + tid;
            int row = f >> 5, c4 = f & 31;
            float4 v = make_float4(0.f, 0.f, 0.f, 0.f);
            if (row < valid)
                v = ((const float4*)io)[(size_t)(base + row) * 32 + c4];
            float h0 = to_tf32(v.x), h1 = to_tf32(v.y);
            float h2 = to_tf32(v.z), h3 = to_tf32(v.w);
            int off = row * 128 + ((c4 ^ (row & 31)) << 2);
            *(float4*)(AHI + off) = make_float4(h0, h1, h2, h3);
            uint32_t p0 = ((uint32_t)__bfloat16_as_ushort(__float2bfloat16(v.y - h1)) << 16)
                        |  (uint32_t)__bfloat16_as_ushort(__float2bfloat16(v.x - h0));
            uint32_t p1 = ((uint32_t)__bfloat16_as_ushort(__float2bfloat16(v.w - h3)) << 16)
                        |  (uint32_t)__bfloat16_as_ushort(__float2bfloat16(v.z - h2));
            uint2 pk; pk.x = p0; pk.y = p1;
            *(uint2*)(ALO + off) = pk;
        }
        __syncthreads();

        // ---- 2) MMA mainloop ------------------------------------------------
        float c[2][8][4];
        #pragma unroll
        for (int u = 0; u < 2; u++)
            #pragma unroll
            for (int j = 0; j < 8; j++)
                #pragma unroll
                for (int e = 0; e < 4; e++) c[u][j][e] = 0.f;

        const int mrow = warp_m * 32 + gid;
        const int nbas = warp_n * 64 + gid;

        #pragma unroll 1
        for (int s = 0; s < 16; s++) {
            const int kb = s << 3;
            uint32_t ah[2][4], al[2][4];
            #pragma unroll
            for (int u = 0; u < 2; u++) {
                int r0 = mrow + u * 16;
                ah[u][0] = __float_as_uint(AHI[idxA(r0,     kb + tig)]);
                ah[u][1] = __float_as_uint(AHI[idxA(r0 + 8, kb + tig)]);
                ah[u][2] = __float_as_uint(AHI[idxA(r0,     kb + 4 + tig)]);
                ah[u][3] = __float_as_uint(AHI[idxA(r0 + 8, kb + 4 + tig)]);
                al[u][0] = __float_as_uint(__bfloat162float(ALO[idxA(r0,     kb + tig)]));
                al[u][1] = __float_as_uint(__bfloat162float(ALO[idxA(r0 + 8, kb + tig)]));
                al[u][2] = __float_as_uint(__bfloat162float(ALO[idxA(r0,     kb + 4 + tig)]));
                al[u][3] = __float_as_uint(__bfloat162float(ALO[idxA(r0 + 8, kb + 4 + tig)]));
            }
            #pragma unroll
            for (int j = 0; j < 8; j++) {
                int n0 = nbas + j * 8;
                uint32_t bh0 = __float_as_uint(WHI[idxA(n0, kb + tig)]);
                uint32_t bh1 = __float_as_uint(WHI[idxA(n0, kb + 4 + tig)]);
                uint32_t bl0 = __float_as_uint(__bfloat162float(WLO[idxA(n0, kb + tig)]));
                uint32_t bl1 = __float_as_uint(__bfloat162float(WLO[idxA(n0, kb + 4 + tig)]));
                #pragma unroll
                for (int u = 0; u < 2; u++) {
                    mma_tf32(c[u][j], ah[u][0], ah[u][1], ah[u][2], ah[u][3], bh0, bh1);
                    mma_tf32(c[u][j], ah[u][0], ah[u][1], ah[u][2], ah[u][3], bl0, bl1);
                    mma_tf32(c[u][j], al[u][0], al[u][1], al[u][2], al[u][3], bh0, bh1);
                }
            }
        }
        __syncthreads();   // all warps done reading AHI/ALO

        // ---- 3) epilogue: bias (+relu) -> out tile (reuse AHI) --------------
        #pragma unroll
        for (int u = 0; u < 2; u++) {
            int r0 = mrow + u * 16;
            #pragma unroll
            for (int j = 0; j < 8; j++) {
                int cc = warp_n * 64 + j * 8 + 2 * tig;
                float v0 = c[u][j][0] + BS[cc];
                float v1 = c[u][j][1] + BS[cc + 1];
                float v2 = c[u][j][2] + BS[cc];
                float v3 = c[u][j][3] + BS[cc + 1];
                if (do_relu) {
                    v0 = fmaxf(v0, 0.f); v1 = fmaxf(v1, 0.f);
                    v2 = fmaxf(v2, 0.f); v3 = fmaxf(v3, 0.f);
                }
                *(float2*)&AHI[idxA(r0,     cc)] = make_float2(v0, v1);
                *(float2*)&AHI[idxA(r0 + 8, cc)] = make_float2(v2, v3);
            }
        }
        __syncthreads();

        // ---- 4) store tile (+ fused BN column sums in stage 2) --------------
        if (do_bn) {
            int col  = tid >> 1;
            int half = tid & 1;
            int rbeg = half * 64;
            int rend = min(rbeg + 64, valid);
            float s = 0.f, q = 0.f;
            for (int r = rbeg; r < rend; r++) {
                float v = AHI[idxA(r, col)];
                s += v; q += v * v;
            }
            atomicAdd(&CS[col], s);
            atomicAdd(&CQ[col], q);
        }
        #pragma unroll
        for (int q = 0; q < 16; q++) {
            int f   = q * STAGE_THREADS + tid;
            int row = f >> 5, c4 = f & 31;
            if (row < valid) {
                int off = row * 128 + ((c4 ^ (row & 31)) << 2);
                float4 v = *(const float4*)(AHI + off);
                ((float4*)io)[(size_t)(base + row) * 32 + c4] = v;
            }
        }
    }

    __syncthreads();
    if (do_bn && tid < 128) {
        atomicAdd(&g_colsum[tid], (double)CS[tid]);
        atomicAdd(&g_colsq [tid], (double)CQ[tid]);
    }
}

// ---------------- BN coefficients -------------------------------------------
__global__ void bn_prep_kernel(const float* __restrict__ gamma,
                               const float* __restrict__ beta) {
    int j = threadIdx.x;
    if (j < D) {
        double mean = g_colsum[j] / (double)N_NODES;
        double var  = g_colsq[j] / (double)N_NODES - mean * mean;
        float inv   = rsqrtf((float)var + EPS);
        float sc    = gamma[j] * inv;
        g_scale[j]  = sc;
        g_shift[j]  = beta[j] - (float)mean * sc;
    }
}

// ---------------- apply BN ----------------------------------------------------
__global__ void bn_apply_kernel(float* __restrict__ out) {
    __shared__ float sc[D], sh[D];
    if (threadIdx.x < D) {
        sc[threadIdx.x] = g_scale[threadIdx.x];
        sh[threadIdx.x] = g_shift[threadIdx.x];
    }
    __syncthreads();
    size_t i  = (size_t)blockIdx.x * blockDim.x + threadIdx.x;
    size_t n4 = (size_t)N_NODES * D / 4;
    if (i < n4) {
        int c = (int)((i & 31) << 2);
        float4 h = reinterpret_cast<const float4*>(g_agg)[i];
        float4 o;
        o.x = h.x * sc[c + 0] + sh[c + 0];
        o.y = h.y * sc[c + 1] + sh[c + 1];
        o.z = h.z * sc[c + 2] + sh[c + 2];
        o.w = h.w * sc[c + 3] + sh[c + 3];
        reinterpret_cast<float4*>(out)[i] = o;
    }
}

// ---------------- launcher ----------------------------------------------------
extern "C" void kernel_launch(void* const* d_in, const int* in_sizes, int n_in,
                              void* d_out, int out_size) {
    const float* x     = (const float*)d_in[0];
    const void*  ei    = d_in[1];
    const float* W1    = (const float*)d_in[2];
    const float* b1    = (const float*)d_in[3];
    const float* W2    = (const float*)d_in[4];
    const float* b2    = (const float*)d_in[5];
    const float* gamma = (const float*)d_in[6];
    const float* beta  = (const float*)d_in[7];
    float* out = (float*)d_out;

    cudaFuncSetAttribute(stage_mma_kernel,
                         cudaFuncAttributeMaxDynamicSharedMemorySize, SM_BYTES);

    detect_kernel<<<1, 32>>>((const int*)ei);
    {
        int n4 = N_NODES * D / 4;
        init_kernel<<<(n4 + 255) / 256, 256>>>(x);
    }
    {
        int blocks = (E_EDGES + 7) / 8;   // 8 warps (256 threads) per block
        scatter_kernel<<<blocks, 256>>>(x, ei);
    }
    stage_mma_kernel<<<152, STAGE_THREADS, SM_BYTES>>>(W1, b1, 1, 0);
    stage_mma_kernel<<<152, STAGE_THREADS, SM_BYTES>>>(W2, b2, 0, 1);
    bn_prep_kernel<<<1, 128>>>(gamma, beta);
    {
        int n4 = N_NODES * D / 4;
        bn_apply_kernel<<<(n4 + 255) / 256, 256>>>(out);
    }
}